// round 1
// baseline (speedup 1.0000x reference)
#include <cuda_runtime.h>

#define BB 4
#define SS 2048
#define DD 1024
#define HH 16
#define HD 64

// Scratch (allocation-free): q in [B,H,S,hd], attention output a in [B,S,D]
__device__ float g_q[(size_t)BB * HH * SS * HD];
__device__ float g_a[(size_t)BB * SS * DD];

// ---------------------------------------------------------------------------
// QKV GEMM: C[m,n] = sum_k x[m,k] * w_attn[n,k] + b_attn[n]
// M=8192, N=3072, K=1024. Epilogue routes q -> g_q, k/v -> present region.
// 64x64 tile, BK=16, 256 threads, 4x4 per thread.
// ---------------------------------------------------------------------------
__global__ __launch_bounds__(256) void qkv_gemm_kernel(
    const float* __restrict__ A, const float* __restrict__ W,
    const float* __restrict__ bias,
    float* __restrict__ kout, float* __restrict__ vout)
{
    __shared__ float As[16][68];
    __shared__ float Bs[16][68];
    const int K = DD;
    const int m0 = blockIdx.y * 64;
    const int n0 = blockIdx.x * 64;
    const int tid = threadIdx.x;
    const int tx = tid & 15, ty = tid >> 4;
    const int lrow = tid >> 2;          // 0..63
    const int lk4  = (tid & 3) << 2;    // 0,4,8,12

    float acc[4][4] = {};

    const float* Ap = A + (size_t)(m0 + lrow) * K + lk4;
    const float* Wp = W + (size_t)(n0 + lrow) * K + lk4;

    for (int k0 = 0; k0 < K; k0 += 16) {
        float4 av = *(const float4*)(Ap + k0);
        float4 bv = *(const float4*)(Wp + k0);
        __syncthreads();
        As[lk4 + 0][lrow] = av.x; As[lk4 + 1][lrow] = av.y;
        As[lk4 + 2][lrow] = av.z; As[lk4 + 3][lrow] = av.w;
        Bs[lk4 + 0][lrow] = bv.x; Bs[lk4 + 1][lrow] = bv.y;
        Bs[lk4 + 2][lrow] = bv.z; Bs[lk4 + 3][lrow] = bv.w;
        __syncthreads();
        #pragma unroll
        for (int kk = 0; kk < 16; kk++) {
            float4 ra = *(const float4*)&As[kk][ty << 2];
            float4 rb = *(const float4*)&Bs[kk][tx << 2];
            float a_[4] = {ra.x, ra.y, ra.z, ra.w};
            float b_[4] = {rb.x, rb.y, rb.z, rb.w};
            #pragma unroll
            for (int i = 0; i < 4; i++)
                #pragma unroll
                for (int j = 0; j < 4; j++)
                    acc[i][j] += a_[i] * b_[j];
        }
    }

    #pragma unroll
    for (int i = 0; i < 4; i++) {
        const int m = m0 + (ty << 2) + i;
        const int b = m >> 11;          // m / SS
        const int s = m & (SS - 1);
        #pragma unroll
        for (int j = 0; j < 4; j++) {
            const int n = n0 + (tx << 2) + j;
            const float v = acc[i][j] + bias[n];
            const int part = n >> 10;           // 0=q, 1=k, 2=v
            const int c = n & (DD - 1);
            const int h = c >> 6;
            const int d = c & 63;
            const size_t dst = (((size_t)(b * HH + h)) * SS + s) * HD + d;
            if (part == 0)      g_q[dst] = v;
            else if (part == 1) kout[dst] = v;
            else                vout[dst] = v;
        }
    }
}

// ---------------------------------------------------------------------------
// Causal flash attention. One thread = one query row. 128 queries / block.
// K/V tiles of 32 keys in SMEM; per-thread online softmax; hd=64 in regs.
// ---------------------------------------------------------------------------
__global__ __launch_bounds__(128) void attn_kernel(
    const float* __restrict__ kbuf, const float* __restrict__ vbuf)
{
    __shared__ float Ks[32 * 64];
    __shared__ float Vs[32 * 64];
    __shared__ float Sx[32 * 128];

    const int tid = threadIdx.x;
    const int bh = blockIdx.y;                       // b*H + h
    const int qrow = blockIdx.x * 128 + tid;

    const float* qp = g_q + ((size_t)bh * SS + qrow) * HD;
    float4 qv[16], acc[16];
    #pragma unroll
    for (int i = 0; i < 16; i++) {
        qv[i] = *(const float4*)(qp + 4 * i);
        acc[i] = make_float4(0.f, 0.f, 0.f, 0.f);
    }

    float mval = -INFINITY, lsum = 0.f;
    const int kend = blockIdx.x * 128 + 128;         // causal bound for block
    const float4* kb4 = (const float4*)(kbuf + (size_t)bh * SS * HD);
    const float4* vb4 = (const float4*)(vbuf + (size_t)bh * SS * HD);

    for (int kt = 0; kt < kend; kt += 32) {
        __syncthreads();
        const int base = kt * (HD / 4);
        #pragma unroll
        for (int i = 0; i < 4; i++) {
            const int idx = tid + i * 128;           // 512 float4 per array
            ((float4*)Ks)[idx] = kb4[base + idx];
            ((float4*)Vs)[idx] = vb4[base + idx];
        }
        __syncthreads();

        // scores for this tile
        float tmax = -INFINITY;
        for (int j = 0; j < 32; j++) {
            const float4* kr = (const float4*)(Ks + j * 64);
            float s0 = 0.f, s1 = 0.f, s2 = 0.f, s3 = 0.f;
            #pragma unroll
            for (int d = 0; d < 16; d++) {
                float4 kv = kr[d];
                s0 += qv[d].x * kv.x; s1 += qv[d].y * kv.y;
                s2 += qv[d].z * kv.z; s3 += qv[d].w * kv.w;
            }
            float sc = ((s0 + s1) + (s2 + s3)) * 0.125f;   // 1/sqrt(64)
            if (kt + j > qrow) sc = -1e30f;                 // causal mask
            Sx[j * 128 + tid] = sc;
            tmax = fmaxf(tmax, sc);
        }

        // online softmax rescale (once per tile)
        const float mnew = fmaxf(mval, tmax);
        const float alpha = __expf(mval - mnew);
        mval = mnew;
        lsum *= alpha;
        #pragma unroll
        for (int i = 0; i < 16; i++) {
            acc[i].x *= alpha; acc[i].y *= alpha;
            acc[i].z *= alpha; acc[i].w *= alpha;
        }

        // P @ V
        for (int j = 0; j < 32; j++) {
            const float p = __expf(Sx[j * 128 + tid] - mval);
            lsum += p;
            const float4* vr = (const float4*)(Vs + j * 64);
            #pragma unroll
            for (int d = 0; d < 16; d++) {
                float4 vv = vr[d];
                acc[d].x += p * vv.x; acc[d].y += p * vv.y;
                acc[d].z += p * vv.z; acc[d].w += p * vv.w;
            }
        }
    }

    const float inv = 1.0f / lsum;
    const int b = bh >> 4, h = bh & 15;
    float4* op = (float4*)(g_a + ((size_t)b * SS + qrow) * DD + h * HD);
    #pragma unroll
    for (int i = 0; i < 16; i++) {
        float4 o;
        o.x = acc[i].x * inv; o.y = acc[i].y * inv;
        o.z = acc[i].z * inv; o.w = acc[i].w * inv;
        op[i] = o;
    }
}

// ---------------------------------------------------------------------------
// Proj GEMM: out[m,n] = sum_k a[m,k] * w_proj[k,n] + b_proj[n]
// M=8192, N=1024, K=1024. W is N-major.
// ---------------------------------------------------------------------------
__global__ __launch_bounds__(256) void proj_gemm_kernel(
    const float* __restrict__ W, const float* __restrict__ bias,
    float* __restrict__ Cout)
{
    __shared__ float As[16][68];
    __shared__ float Bs[16][68];
    const int K = DD, N = DD;
    const int m0 = blockIdx.y * 64;
    const int n0 = blockIdx.x * 64;
    const int tid = threadIdx.x;
    const int tx = tid & 15, ty = tid >> 4;
    const int lrow = tid >> 2;
    const int lk4  = (tid & 3) << 2;
    const int bk = tid >> 4;             // 0..15
    const int bn = (tid & 15) << 2;      // 0..60

    float acc[4][4] = {};

    const float* Ap = g_a + (size_t)(m0 + lrow) * K + lk4;
    const float* Wp = W + (size_t)bk * N + n0 + bn;

    for (int k0 = 0; k0 < K; k0 += 16) {
        float4 av = *(const float4*)(Ap + k0);
        float4 bv = *(const float4*)(Wp + (size_t)k0 * N);
        __syncthreads();
        As[lk4 + 0][lrow] = av.x; As[lk4 + 1][lrow] = av.y;
        As[lk4 + 2][lrow] = av.z; As[lk4 + 3][lrow] = av.w;
        *(float4*)&Bs[bk][bn] = bv;
        __syncthreads();
        #pragma unroll
        for (int kk = 0; kk < 16; kk++) {
            float4 ra = *(const float4*)&As[kk][ty << 2];
            float4 rb = *(const float4*)&Bs[kk][tx << 2];
            float a_[4] = {ra.x, ra.y, ra.z, ra.w};
            float b_[4] = {rb.x, rb.y, rb.z, rb.w};
            #pragma unroll
            for (int i = 0; i < 4; i++)
                #pragma unroll
                for (int j = 0; j < 4; j++)
                    acc[i][j] += a_[i] * b_[j];
        }
    }

    #pragma unroll
    for (int i = 0; i < 4; i++) {
        const int m = m0 + (ty << 2) + i;
        #pragma unroll
        for (int j = 0; j < 4; j++) {
            const int n = n0 + (tx << 2) + j;
            Cout[(size_t)m * DD + n] = acc[i][j] + bias[n];
        }
    }
}

// ---------------------------------------------------------------------------
extern "C" void kernel_launch(void* const* d_in, const int* in_sizes, int n_in,
                              void* d_out, int out_size)
{
    const float* x      = (const float*)d_in[0];
    const float* w_attn = (const float*)d_in[1];
    const float* b_attn = (const float*)d_in[2];
    const float* w_proj = (const float*)d_in[3];
    const float* b_proj = (const float*)d_in[4];

    float* out  = (float*)d_out;                              // [B,S,D]
    float* kout = out + (size_t)BB * SS * DD;                 // present[0] = k
    float* vout = kout + (size_t)BB * HH * SS * HD;           // present[1] = v

    // 1) QKV projection (q -> g_q, k/v -> present region of d_out)
    dim3 g1(3 * DD / 64, (BB * SS) / 64);   // (48, 128)
    qkv_gemm_kernel<<<g1, 256>>>(x, w_attn, b_attn, kout, vout);

    // 2) Causal flash attention -> g_a (merged heads [B,S,D])
    dim3 g2(SS / 128, BB * HH);             // (16, 64)
    attn_kernel<<<g2, 128>>>(kout, vout);

    // 3) Output projection -> out
    dim3 g3(DD / 64, (BB * SS) / 64);       // (16, 128)
    proj_gemm_kernel<<<g3, 256>>>(w_proj, b_proj, out);
}

// round 3
// speedup vs baseline: 1.6124x; 1.6124x over previous
#include <cuda_runtime.h>
#include <cstdint>

#define BB 4
#define SS 2048
#define DD 1024
#define HH 16
#define HD 64

// Scratch (allocation-free)
__device__ float g_q[(size_t)BB * HH * SS * HD];   // q [B,H,S,hd]
__device__ float g_a[(size_t)BB * SS * DD];        // attention out (tf32-rounded)
__device__ float g_xr[(size_t)BB * SS * DD];       // x rounded to tf32
__device__ float g_war[(size_t)3 * DD * DD];       // w_attn rounded to tf32
__device__ float g_wt[(size_t)DD * DD];            // w_proj^T rounded to tf32

// ---------------------------------------------------------------------------
__device__ __forceinline__ uint32_t smem_u32(const void* p) {
    uint32_t a;
    asm("{ .reg .u64 t; cvta.to.shared.u64 t, %1; cvt.u32.u64 %0, t; }"
        : "=r"(a) : "l"(p));
    return a;
}
__device__ __forceinline__ uint32_t f2tf(float f) {
    uint32_t u;
    asm("cvt.rna.tf32.f32 %0, %1;" : "=r"(u) : "f"(f));
    return u;
}
__device__ __forceinline__ void cp_async16(uint32_t dst, const void* src) {
    asm volatile("cp.async.cg.shared.global [%0], [%1], 16;" :: "r"(dst), "l"(src));
}
#define CP_COMMIT() asm volatile("cp.async.commit_group;" ::: "memory")
#define CP_WAIT(n)  asm volatile("cp.async.wait_group %0;" :: "n"(n) : "memory")

__device__ __forceinline__ void mma_tf32(float* c, const uint32_t* a, const uint32_t* b) {
    asm volatile(
        "mma.sync.aligned.m16n8k8.row.col.f32.tf32.tf32.f32 "
        "{%0,%1,%2,%3}, {%4,%5,%6,%7}, {%8,%9}, {%0,%1,%2,%3};"
        : "+f"(c[0]), "+f"(c[1]), "+f"(c[2]), "+f"(c[3])
        : "r"(a[0]), "r"(a[1]), "r"(a[2]), "r"(a[3]), "r"(b[0]), "r"(b[1]));
}

// ---------------------------------------------------------------------------
// Elementwise round-to-tf32 (float4 grid-stride)
// ---------------------------------------------------------------------------
__global__ __launch_bounds__(256) void round_kernel(
    const float4* __restrict__ in, float4* __restrict__ out, int n4)
{
    int i = blockIdx.x * blockDim.x + threadIdx.x;
    int stride = gridDim.x * blockDim.x;
    for (; i < n4; i += stride) {
        float4 v = in[i];
        float4 o;
        o.x = __uint_as_float(f2tf(v.x));
        o.y = __uint_as_float(f2tf(v.y));
        o.z = __uint_as_float(f2tf(v.z));
        o.w = __uint_as_float(f2tf(v.w));
        out[i] = o;
    }
}

// w_proj [K,N] -> g_wt [N,K], rounded to tf32
__global__ __launch_bounds__(256) void transpose_round_kernel(
    const float* __restrict__ in, float* __restrict__ out)
{
    __shared__ float t[32][33];
    const int tx = threadIdx.x, ty = threadIdx.y;
    const int k0 = blockIdx.y * 32;
    const int n0 = blockIdx.x * 32;
#pragma unroll
    for (int i = ty; i < 32; i += 8)
        t[i][tx] = in[(size_t)(k0 + i) * DD + n0 + tx];
    __syncthreads();
#pragma unroll
    for (int i = ty; i < 32; i += 8)
        out[(size_t)(n0 + i) * DD + k0 + tx] = __uint_as_float(f2tf(t[tx][i]));
}

// ---------------------------------------------------------------------------
// tf32 mma.sync GEMM: C[m,n] = sum_k A[m,k]*B[n,k] + bias[n]  (A,B pre-rounded)
// CTA tile 128x128, BK=32, 3-stage cp.async pipeline, 8 warps x (32x64).
// MODE 0: C -> out0[m*DD+n].   MODE 1: qkv routing q->g_q, k->out1, v->out2.
// ---------------------------------------------------------------------------
#define KDIM 1024
#define NCHUNK (KDIM / 32)
#define STG_F 9216                 // floats per stage: (128+128)*36
#define ROWSTRIDE 36
#define GEMM_SMEM (3 * STG_F * 4)  // 110592 bytes

template <int MODE>
__global__ __launch_bounds__(256, 1) void mma_gemm(
    const float* __restrict__ A, const float* __restrict__ Bm,
    const float* __restrict__ bias,
    float* __restrict__ out0, float* __restrict__ out1, float* __restrict__ out2)
{
    extern __shared__ float sm[];
    const uint32_t sbase = smem_u32(sm);
    const int tid = threadIdx.x;
    const int wid = tid >> 5;
    const int lane = tid & 31;
    const int g = lane >> 2;         // 0..7
    const int tig = lane & 3;        // 0..3
    const int m0 = blockIdx.y * 128;
    const int n0 = blockIdx.x * 128;
    const int wm = (wid & 3) * 32;   // warp m offset in tile
    const int wn = (wid >> 2) * 64;  // warp n offset in tile

    float c[2][8][4];
#pragma unroll
    for (int i = 0; i < 2; i++)
#pragma unroll
        for (int j = 0; j < 8; j++)
#pragma unroll
            for (int k = 0; k < 4; k++) c[i][j][k] = 0.f;

    // loader: 4 float4 per matrix per chunk per thread
    const int lrow = tid >> 3;            // 0..31 (+32*i)
    const int lcol = (tid & 7) * 4;       // 0..28
    const float* Abase = A + (size_t)m0 * KDIM;
    const float* Bbase = Bm + (size_t)n0 * KDIM;

#define ISSUE(chunk, s) do {                                                        \
    const int _k0 = (chunk) * 32;                                                   \
    const uint32_t _as = sbase + (uint32_t)(s) * STG_F * 4;                         \
    const uint32_t _bs = _as + 4608 * 4;                                            \
    _Pragma("unroll")                                                               \
    for (int _i = 0; _i < 4; _i++) {                                                \
        const int _r = lrow + _i * 32;                                              \
        cp_async16(_as + (uint32_t)(_r * ROWSTRIDE + lcol) * 4,                     \
                   Abase + (size_t)_r * KDIM + _k0 + lcol);                         \
        cp_async16(_bs + (uint32_t)(_r * ROWSTRIDE + lcol) * 4,                     \
                   Bbase + (size_t)_r * KDIM + _k0 + lcol);                         \
    }                                                                               \
    CP_COMMIT();                                                                    \
} while (0)

    ISSUE(0, 0);
    ISSUE(1, 1);

    for (int ch = 0; ch < NCHUNK; ch++) {
        const int s = ch % 3;
        if (ch + 2 < NCHUNK) {
            ISSUE(ch + 2, (ch + 2) % 3);
            CP_WAIT(2);
        } else if (ch + 1 < NCHUNK) {
            CP_WAIT(1);
        } else {
            CP_WAIT(0);
        }
        __syncthreads();

        const float* As_ = sm + s * STG_F;
        const float* Bs_ = sm + s * STG_F + 4608;
#pragma unroll
        for (int ks = 0; ks < 4; ks++) {
            const int kc = ks * 8 + tig;
            uint32_t af[2][4], bf[8][2];
#pragma unroll
            for (int mt = 0; mt < 2; mt++) {
                const int r = wm + mt * 16 + g;
                af[mt][0] = __float_as_uint(As_[r * ROWSTRIDE + kc]);
                af[mt][1] = __float_as_uint(As_[(r + 8) * ROWSTRIDE + kc]);
                af[mt][2] = __float_as_uint(As_[r * ROWSTRIDE + kc + 4]);
                af[mt][3] = __float_as_uint(As_[(r + 8) * ROWSTRIDE + kc + 4]);
            }
#pragma unroll
            for (int nt = 0; nt < 8; nt++) {
                const int rn = wn + nt * 8 + g;
                bf[nt][0] = __float_as_uint(Bs_[rn * ROWSTRIDE + kc]);
                bf[nt][1] = __float_as_uint(Bs_[rn * ROWSTRIDE + kc + 4]);
            }
#pragma unroll
            for (int mt = 0; mt < 2; mt++)
#pragma unroll
                for (int nt = 0; nt < 8; nt++)
                    mma_tf32(c[mt][nt], af[mt], bf[nt]);
        }
        __syncthreads();
    }

    // Epilogue: bias + store (float2 per row-pair per tile)
#pragma unroll
    for (int mt = 0; mt < 2; mt++) {
        const int row0 = m0 + wm + mt * 16 + g;
        const int row1 = row0 + 8;
#pragma unroll
        for (int nt = 0; nt < 8; nt++) {
            const int n = n0 + wn + nt * 8 + 2 * tig;
            const float2 bv = *(const float2*)(bias + n);
            float2 v0, v1;
            v0.x = c[mt][nt][0] + bv.x; v0.y = c[mt][nt][1] + bv.y;
            v1.x = c[mt][nt][2] + bv.x; v1.y = c[mt][nt][3] + bv.y;
            if (MODE == 0) {
                *(float2*)(out0 + (size_t)row0 * DD + n) = v0;
                *(float2*)(out1 + (size_t)row1 * DD + n) = v1;   // out1 == out0 here
            } else {
                const int part = n >> 10;
                const int hc = n & (DD - 1);
                const int h = hc >> 6;
                const int d = hc & 63;
                const int b0_ = row0 >> 11, s0_ = row0 & (SS - 1);
                const int b1_ = row1 >> 11, s1_ = row1 & (SS - 1);
                const size_t d0 = (((size_t)(b0_ * HH + h)) * SS + s0_) * HD + d;
                const size_t d1 = (((size_t)(b1_ * HH + h)) * SS + s1_) * HD + d;
                float* p0; float* p1;
                if (part == 0)      { p0 = g_q;  p1 = g_q;  }
                else if (part == 1) { p0 = out1; p1 = out1; }
                else                { p0 = out2; p1 = out2; }
                *(float2*)(p0 + d0) = v0;
                *(float2*)(p1 + d1) = v1;
            }
        }
    }
}

// ---------------------------------------------------------------------------
// Causal flash attention (fp32). One thread = one query row.
// Epilogue rounds output to tf32 (it feeds the proj GEMM).
// ---------------------------------------------------------------------------
__global__ __launch_bounds__(128) void attn_kernel(
    const float* __restrict__ kbuf, const float* __restrict__ vbuf)
{
    __shared__ float Ks[32 * 64];
    __shared__ float Vs[32 * 64];
    __shared__ float Sx[32 * 128];

    const int tid = threadIdx.x;
    const int bh = blockIdx.y;
    const int qrow = blockIdx.x * 128 + tid;

    const float* qp = g_q + ((size_t)bh * SS + qrow) * HD;
    float4 qv[16], acc[16];
#pragma unroll
    for (int i = 0; i < 16; i++) {
        qv[i] = *(const float4*)(qp + 4 * i);
        acc[i] = make_float4(0.f, 0.f, 0.f, 0.f);
    }

    float mval = -INFINITY, lsum = 0.f;
    const int kend = blockIdx.x * 128 + 128;
    const float4* kb4 = (const float4*)(kbuf + (size_t)bh * SS * HD);
    const float4* vb4 = (const float4*)(vbuf + (size_t)bh * SS * HD);

    for (int kt = 0; kt < kend; kt += 32) {
        __syncthreads();
        const int base = kt * (HD / 4);
#pragma unroll
        for (int i = 0; i < 4; i++) {
            const int idx = tid + i * 128;
            ((float4*)Ks)[idx] = kb4[base + idx];
            ((float4*)Vs)[idx] = vb4[base + idx];
        }
        __syncthreads();

        float tmax = -INFINITY;
        for (int j = 0; j < 32; j++) {
            const float4* kr = (const float4*)(Ks + j * 64);
            float s0 = 0.f, s1 = 0.f, s2 = 0.f, s3 = 0.f;
#pragma unroll
            for (int d = 0; d < 16; d++) {
                float4 kv = kr[d];
                s0 += qv[d].x * kv.x; s1 += qv[d].y * kv.y;
                s2 += qv[d].z * kv.z; s3 += qv[d].w * kv.w;
            }
            float sc = ((s0 + s1) + (s2 + s3)) * 0.125f;
            if (kt + j > qrow) sc = -1e30f;
            Sx[j * 128 + tid] = sc;
            tmax = fmaxf(tmax, sc);
        }

        const float mnew = fmaxf(mval, tmax);
        const float alpha = __expf(mval - mnew);
        mval = mnew;
        lsum *= alpha;
#pragma unroll
        for (int i = 0; i < 16; i++) {
            acc[i].x *= alpha; acc[i].y *= alpha;
            acc[i].z *= alpha; acc[i].w *= alpha;
        }

        for (int j = 0; j < 32; j++) {
            const float p = __expf(Sx[j * 128 + tid] - mval);
            lsum += p;
            const float4* vr = (const float4*)(Vs + j * 64);
#pragma unroll
            for (int d = 0; d < 16; d++) {
                float4 vv = vr[d];
                acc[d].x += p * vv.x; acc[d].y += p * vv.y;
                acc[d].z += p * vv.z; acc[d].w += p * vv.w;
            }
        }
    }

    const float inv = 1.0f / lsum;
    const int b = bh >> 4, h = bh & 15;
    float4* op = (float4*)(g_a + ((size_t)b * SS + qrow) * DD + h * HD);
#pragma unroll
    for (int i = 0; i < 16; i++) {
        float4 o;
        o.x = __uint_as_float(f2tf(acc[i].x * inv));
        o.y = __uint_as_float(f2tf(acc[i].y * inv));
        o.z = __uint_as_float(f2tf(acc[i].z * inv));
        o.w = __uint_as_float(f2tf(acc[i].w * inv));
        op[i] = o;
    }
}

// ---------------------------------------------------------------------------
extern "C" void kernel_launch(void* const* d_in, const int* in_sizes, int n_in,
                              void* d_out, int out_size)
{
    const float* x      = (const float*)d_in[0];
    const float* w_attn = (const float*)d_in[1];
    const float* b_attn = (const float*)d_in[2];
    const float* w_proj = (const float*)d_in[3];
    const float* b_proj = (const float*)d_in[4];

    float* out  = (float*)d_out;
    float* kout = out + (size_t)BB * SS * DD;
    float* vout = kout + (size_t)BB * HH * SS * HD;

    float *xr, *war, *wt, *ga;
    cudaGetSymbolAddress((void**)&xr, g_xr);
    cudaGetSymbolAddress((void**)&war, g_war);
    cudaGetSymbolAddress((void**)&wt, g_wt);
    cudaGetSymbolAddress((void**)&ga, g_a);

    cudaFuncSetAttribute(mma_gemm<0>, cudaFuncAttributeMaxDynamicSharedMemorySize, GEMM_SMEM);
    cudaFuncSetAttribute(mma_gemm<1>, cudaFuncAttributeMaxDynamicSharedMemorySize, GEMM_SMEM);

    // Pre-round GEMM inputs to tf32
    round_kernel<<<1024, 256>>>((const float4*)x, (float4*)xr, BB * SS * DD / 4);
    round_kernel<<<1024, 256>>>((const float4*)w_attn, (float4*)war, 3 * DD * DD / 4);
    transpose_round_kernel<<<dim3(32, 32), dim3(32, 8)>>>(w_proj, wt);

    // QKV GEMM: [8192,1024] x [3072,1024]^T. q->g_q, k/v->present.
    mma_gemm<1><<<dim3(3 * DD / 128, BB * SS / 128), 256, GEMM_SMEM>>>(
        xr, war, b_attn, nullptr, kout, vout);

    // Attention -> g_a (tf32-rounded)
    attn_kernel<<<dim3(SS / 128, BB * HH), 128>>>(kout, vout);

    // Proj GEMM: [8192,1024] x [1024,1024]^T -> out
    mma_gemm<0><<<dim3(DD / 128, BB * SS / 128), 256, GEMM_SMEM>>>(
        ga, wt, b_proj, out, out, nullptr);
}

// round 4
// speedup vs baseline: 3.7244x; 2.3098x over previous
#include <cuda_runtime.h>
#include <cstdint>

#define BB 4
#define SS 2048
#define DD 1024
#define HH 16
#define HD 64

// Scratch (allocation-free)
__device__ float g_q[(size_t)BB * HH * SS * HD];   // q [B,H,S,hd] (tf32-rounded, pre-scaled? no: raw rounded)
__device__ float g_a[(size_t)BB * SS * DD];        // attention out (tf32-rounded)
__device__ float g_xr[(size_t)BB * SS * DD];       // x rounded to tf32
__device__ float g_war[(size_t)3 * DD * DD];       // w_attn rounded to tf32
__device__ float g_wt[(size_t)DD * DD];            // w_proj^T rounded to tf32
__device__ float g_kr[(size_t)BB * HH * SS * HD];  // k rounded (attention input)
__device__ float g_vr[(size_t)BB * HH * SS * HD];  // v rounded (attention input)

// ---------------------------------------------------------------------------
__device__ __forceinline__ uint32_t smem_u32(const void* p) {
    uint32_t a;
    asm("{ .reg .u64 t; cvta.to.shared.u64 t, %1; cvt.u32.u64 %0, t; }"
        : "=r"(a) : "l"(p));
    return a;
}
__device__ __forceinline__ uint32_t f2tf(float f) {
    uint32_t u;
    asm("cvt.rna.tf32.f32 %0, %1;" : "=r"(u) : "f"(f));
    return u;
}
__device__ __forceinline__ void cp_async16(uint32_t dst, const void* src) {
    asm volatile("cp.async.cg.shared.global [%0], [%1], 16;" :: "r"(dst), "l"(src));
}
#define CP_COMMIT() asm volatile("cp.async.commit_group;" ::: "memory")
#define CP_WAIT(n)  asm volatile("cp.async.wait_group %0;" :: "n"(n) : "memory")

__device__ __forceinline__ void mma_tf32(float* c, const uint32_t* a, const uint32_t* b) {
    asm volatile(
        "mma.sync.aligned.m16n8k8.row.col.f32.tf32.tf32.f32 "
        "{%0,%1,%2,%3}, {%4,%5,%6,%7}, {%8,%9}, {%0,%1,%2,%3};"
        : "+f"(c[0]), "+f"(c[1]), "+f"(c[2]), "+f"(c[3])
        : "r"(a[0]), "r"(a[1]), "r"(a[2]), "r"(a[3]), "r"(b[0]), "r"(b[1]));
}

// ---------------------------------------------------------------------------
// Elementwise round-to-tf32
// ---------------------------------------------------------------------------
__global__ __launch_bounds__(256) void round_kernel(
    const float4* __restrict__ in, float4* __restrict__ out, int n4)
{
    int i = blockIdx.x * blockDim.x + threadIdx.x;
    int stride = gridDim.x * blockDim.x;
    for (; i < n4; i += stride) {
        float4 v = in[i];
        float4 o;
        o.x = __uint_as_float(f2tf(v.x));
        o.y = __uint_as_float(f2tf(v.y));
        o.z = __uint_as_float(f2tf(v.z));
        o.w = __uint_as_float(f2tf(v.w));
        out[i] = o;
    }
}

__global__ __launch_bounds__(256) void transpose_round_kernel(
    const float* __restrict__ in, float* __restrict__ out)
{
    __shared__ float t[32][33];
    const int tx = threadIdx.x, ty = threadIdx.y;
    const int k0 = blockIdx.y * 32;
    const int n0 = blockIdx.x * 32;
#pragma unroll
    for (int i = ty; i < 32; i += 8)
        t[i][tx] = in[(size_t)(k0 + i) * DD + n0 + tx];
    __syncthreads();
#pragma unroll
    for (int i = ty; i < 32; i += 8)
        out[(size_t)(n0 + i) * DD + k0 + tx] = __uint_as_float(f2tf(t[tx][i]));
}

// ---------------------------------------------------------------------------
// tf32 mma.sync GEMM (unchanged from round 3)
// ---------------------------------------------------------------------------
#define KDIM 1024
#define NCHUNK (KDIM / 32)
#define STG_F 9216
#define ROWSTRIDE 36
#define GEMM_SMEM (3 * STG_F * 4)

template <int MODE>
__global__ __launch_bounds__(256, 1) void mma_gemm(
    const float* __restrict__ A, const float* __restrict__ Bm,
    const float* __restrict__ bias,
    float* __restrict__ out0, float* __restrict__ out1, float* __restrict__ out2)
{
    extern __shared__ float sm[];
    const uint32_t sbase = smem_u32(sm);
    const int tid = threadIdx.x;
    const int wid = tid >> 5;
    const int lane = tid & 31;
    const int g = lane >> 2;
    const int tig = lane & 3;
    const int m0 = blockIdx.y * 128;
    const int n0 = blockIdx.x * 128;
    const int wm = (wid & 3) * 32;
    const int wn = (wid >> 2) * 64;

    float c[2][8][4];
#pragma unroll
    for (int i = 0; i < 2; i++)
#pragma unroll
        for (int j = 0; j < 8; j++)
#pragma unroll
            for (int k = 0; k < 4; k++) c[i][j][k] = 0.f;

    const int lrow = tid >> 3;
    const int lcol = (tid & 7) * 4;
    const float* Abase = A + (size_t)m0 * KDIM;
    const float* Bbase = Bm + (size_t)n0 * KDIM;

#define ISSUE(chunk, s) do {                                                        \
    const int _k0 = (chunk) * 32;                                                   \
    const uint32_t _as = sbase + (uint32_t)(s) * STG_F * 4;                         \
    const uint32_t _bs = _as + 4608 * 4;                                            \
    _Pragma("unroll")                                                               \
    for (int _i = 0; _i < 4; _i++) {                                                \
        const int _r = lrow + _i * 32;                                              \
        cp_async16(_as + (uint32_t)(_r * ROWSTRIDE + lcol) * 4,                     \
                   Abase + (size_t)_r * KDIM + _k0 + lcol);                         \
        cp_async16(_bs + (uint32_t)(_r * ROWSTRIDE + lcol) * 4,                     \
                   Bbase + (size_t)_r * KDIM + _k0 + lcol);                         \
    }                                                                               \
    CP_COMMIT();                                                                    \
} while (0)

    ISSUE(0, 0);
    ISSUE(1, 1);

    for (int ch = 0; ch < NCHUNK; ch++) {
        const int s = ch % 3;
        if (ch + 2 < NCHUNK) {
            ISSUE(ch + 2, (ch + 2) % 3);
            CP_WAIT(2);
        } else if (ch + 1 < NCHUNK) {
            CP_WAIT(1);
        } else {
            CP_WAIT(0);
        }
        __syncthreads();

        const float* As_ = sm + s * STG_F;
        const float* Bs_ = sm + s * STG_F + 4608;
#pragma unroll
        for (int ks = 0; ks < 4; ks++) {
            const int kc = ks * 8 + tig;
            uint32_t af[2][4], bf[8][2];
#pragma unroll
            for (int mt = 0; mt < 2; mt++) {
                const int r = wm + mt * 16 + g;
                af[mt][0] = __float_as_uint(As_[r * ROWSTRIDE + kc]);
                af[mt][1] = __float_as_uint(As_[(r + 8) * ROWSTRIDE + kc]);
                af[mt][2] = __float_as_uint(As_[r * ROWSTRIDE + kc + 4]);
                af[mt][3] = __float_as_uint(As_[(r + 8) * ROWSTRIDE + kc + 4]);
            }
#pragma unroll
            for (int nt = 0; nt < 8; nt++) {
                const int rn = wn + nt * 8 + g;
                bf[nt][0] = __float_as_uint(Bs_[rn * ROWSTRIDE + kc]);
                bf[nt][1] = __float_as_uint(Bs_[rn * ROWSTRIDE + kc + 4]);
            }
#pragma unroll
            for (int mt = 0; mt < 2; mt++)
#pragma unroll
                for (int nt = 0; nt < 8; nt++)
                    mma_tf32(c[mt][nt], af[mt], bf[nt]);
        }
        __syncthreads();
    }

#pragma unroll
    for (int mt = 0; mt < 2; mt++) {
        const int row0 = m0 + wm + mt * 16 + g;
        const int row1 = row0 + 8;
#pragma unroll
        for (int nt = 0; nt < 8; nt++) {
            const int n = n0 + wn + nt * 8 + 2 * tig;
            const float2 bv = *(const float2*)(bias + n);
            float2 v0, v1;
            v0.x = c[mt][nt][0] + bv.x; v0.y = c[mt][nt][1] + bv.y;
            v1.x = c[mt][nt][2] + bv.x; v1.y = c[mt][nt][3] + bv.y;
            if (MODE == 0) {
                *(float2*)(out0 + (size_t)row0 * DD + n) = v0;
                *(float2*)(out0 + (size_t)row1 * DD + n) = v1;
            } else {
                const int part = n >> 10;
                const int hc = n & (DD - 1);
                const int h = hc >> 6;
                const int d = hc & 63;
                const int b0_ = row0 >> 11, s0_ = row0 & (SS - 1);
                const int b1_ = row1 >> 11, s1_ = row1 & (SS - 1);
                const size_t d0 = (((size_t)(b0_ * HH + h)) * SS + s0_) * HD + d;
                const size_t d1 = (((size_t)(b1_ * HH + h)) * SS + s1_) * HD + d;
                if (part == 0) {
                    // q: pre-round to tf32 for the attention mma
                    v0.x = __uint_as_float(f2tf(v0.x)); v0.y = __uint_as_float(f2tf(v0.y));
                    v1.x = __uint_as_float(f2tf(v1.x)); v1.y = __uint_as_float(f2tf(v1.y));
                    *(float2*)(g_q + d0) = v0;
                    *(float2*)(g_q + d1) = v1;
                } else if (part == 1) {
                    *(float2*)(out1 + d0) = v0;
                    *(float2*)(out1 + d1) = v1;
                } else {
                    *(float2*)(out2 + d0) = v0;
                    *(float2*)(out2 + d1) = v1;
                }
            }
        }
    }
}

// ---------------------------------------------------------------------------
// Tensor-core causal flash attention.
// CTA: 128 threads (4 warps), 64 queries. Key tiles of 64, cp.async x2 stages.
// Ks/Vs stride 72 floats; Ps stride 68 floats.
// ---------------------------------------------------------------------------
#define KSTR 72
#define PSTR 68
#define AKS_OFF(s) ((uint32_t)(s) * 18432u)
#define AVS_OFF(s) (36864u + (uint32_t)(s) * 18432u)
#define APS_OFF 73728u
#define ATT_SMEM (APS_OFF + 64u * PSTR * 4u)   // 91136 bytes

__global__ __launch_bounds__(128, 2) void attn_tc(
    const float* __restrict__ kr, const float* __restrict__ vr)
{
    extern __shared__ char smc[];
    float* smf = (float*)smc;
    const uint32_t sb = smem_u32(smc);
    const int tid = threadIdx.x;
    const int w = tid >> 5, lane = tid & 31;
    const int g = lane >> 2, tig = lane & 3;
    const int bh = blockIdx.x;
    const int qblk = blockIdx.y;
    const int q0 = qblk * 64;
    const float* kbase = kr + (size_t)bh * SS * HD;
    const float* vbase = vr + (size_t)bh * SS * HD;

#define AISSUE(t) do {                                                            \
    const int _st = (t) & 1;                                                      \
    const int _k0 = (t) * 64;                                                     \
    _Pragma("unroll")                                                             \
    for (int _i = 0; _i < 8; _i++) {                                              \
        const int _f = tid + 128 * _i;                                            \
        const int _r = _f >> 4;                                                   \
        const int _c = (_f & 15) << 2;                                            \
        cp_async16(sb + AKS_OFF(_st) + (uint32_t)(_r * KSTR + _c) * 4,            \
                   kbase + (size_t)(_k0 + _r) * HD + _c);                         \
        cp_async16(sb + AVS_OFF(_st) + (uint32_t)(_r * KSTR + _c) * 4,            \
                   vbase + (size_t)(_k0 + _r) * HD + _c);                         \
    }                                                                             \
    CP_COMMIT();                                                                  \
} while (0)

    // Stage Q (64x64) into Ps region
    {
        const float* qbase = g_q + ((size_t)bh * SS + q0) * HD;
#pragma unroll
        for (int i = 0; i < 8; i++) {
            const int f = tid + 128 * i;
            const int r = f >> 4;
            const int c = (f & 15) << 2;
            cp_async16(sb + APS_OFF + (uint32_t)(r * PSTR + c) * 4,
                       qbase + (size_t)r * HD + c);
        }
        CP_COMMIT();
    }
    AISSUE(0);
    CP_WAIT(1);            // Q staged (K0/V0 may still be in flight)
    __syncthreads();

    // Q fragments (pre-scaled by 1/sqrt(hd)=0.125; exact power of 2)
    uint32_t qa[8][4];
    {
        const int r0 = w * 16 + g;
        const float* Q = smf + APS_OFF / 4;
#pragma unroll
        for (int kc = 0; kc < 8; kc++) {
            qa[kc][0] = __float_as_uint(Q[r0 * PSTR + kc * 8 + tig] * 0.125f);
            qa[kc][1] = __float_as_uint(Q[(r0 + 8) * PSTR + kc * 8 + tig] * 0.125f);
            qa[kc][2] = __float_as_uint(Q[r0 * PSTR + kc * 8 + tig + 4] * 0.125f);
            qa[kc][3] = __float_as_uint(Q[(r0 + 8) * PSTR + kc * 8 + tig + 4] * 0.125f);
        }
    }
    __syncthreads();       // done reading Q from Ps region

    float o[8][4];
#pragma unroll
    for (int i = 0; i < 8; i++)
#pragma unroll
        for (int j = 0; j < 4; j++) o[i][j] = 0.f;
    float m0 = -1e30f, m1 = -1e30f, l0 = 0.f, l1 = 0.f;

    const int r0 = w * 16 + g;                  // local query rows r0, r0+8

    for (int t = 0; t <= qblk; t++) {
        const int st = t & 1;
        if (t + 1 <= qblk) AISSUE(t + 1);
        if (t < qblk) { CP_WAIT(1); } else { CP_WAIT(0); }
        __syncthreads();

        // --- S = (Q/8) @ K^T
        float s[8][4];
#pragma unroll
        for (int i = 0; i < 8; i++)
#pragma unroll
            for (int j = 0; j < 4; j++) s[i][j] = 0.f;

        const float* Ks = smf + AKS_OFF(st) / 4;
#pragma unroll
        for (int kc = 0; kc < 8; kc++) {
            uint32_t kb[8][2];
#pragma unroll
            for (int nt = 0; nt < 8; nt++) {
                kb[nt][0] = __float_as_uint(Ks[(8 * nt + g) * KSTR + 8 * kc + tig]);
                kb[nt][1] = __float_as_uint(Ks[(8 * nt + g) * KSTR + 8 * kc + tig + 4]);
            }
#pragma unroll
            for (int nt = 0; nt < 8; nt++)
                mma_tf32(s[nt], qa[kc], kb[nt]);
        }

        // --- causal mask on diagonal tile
        if (t == qblk) {
#pragma unroll
            for (int nt = 0; nt < 8; nt++) {
                const int col = 8 * nt + 2 * tig;
                if (col > r0)         s[nt][0] = -1e30f;
                if (col + 1 > r0)     s[nt][1] = -1e30f;
                if (col > r0 + 8)     s[nt][2] = -1e30f;
                if (col + 1 > r0 + 8) s[nt][3] = -1e30f;
            }
        }

        // --- row max (reduce over this thread, then over the 4 lanes of the group)
        float mx0 = -1e30f, mx1 = -1e30f;
#pragma unroll
        for (int nt = 0; nt < 8; nt++) {
            mx0 = fmaxf(mx0, fmaxf(s[nt][0], s[nt][1]));
            mx1 = fmaxf(mx1, fmaxf(s[nt][2], s[nt][3]));
        }
        mx0 = fmaxf(mx0, __shfl_xor_sync(0xffffffffu, mx0, 1));
        mx0 = fmaxf(mx0, __shfl_xor_sync(0xffffffffu, mx0, 2));
        mx1 = fmaxf(mx1, __shfl_xor_sync(0xffffffffu, mx1, 1));
        mx1 = fmaxf(mx1, __shfl_xor_sync(0xffffffffu, mx1, 2));

        const float mn0 = fmaxf(m0, mx0);
        const float mn1 = fmaxf(m1, mx1);
        const float a0 = __expf(m0 - mn0);
        const float a1 = __expf(m1 - mn1);
        m0 = mn0; m1 = mn1;
        l0 *= a0; l1 *= a1;
#pragma unroll
        for (int nt = 0; nt < 8; nt++) {
            o[nt][0] *= a0; o[nt][1] *= a0;
            o[nt][2] *= a1; o[nt][3] *= a1;
        }

        // --- exp, write P (tf32-rounded) to smem, accumulate row sums
        float* Ps = smf + APS_OFF / 4;
        float rs0 = 0.f, rs1 = 0.f;
#pragma unroll
        for (int nt = 0; nt < 8; nt++) {
            const float p0 = __expf(s[nt][0] - mn0);
            const float p1 = __expf(s[nt][1] - mn0);
            const float p2 = __expf(s[nt][2] - mn1);
            const float p3 = __expf(s[nt][3] - mn1);
            rs0 += p0 + p1;
            rs1 += p2 + p3;
            float2 w0, w1;
            w0.x = __uint_as_float(f2tf(p0)); w0.y = __uint_as_float(f2tf(p1));
            w1.x = __uint_as_float(f2tf(p2)); w1.y = __uint_as_float(f2tf(p3));
            *(float2*)(Ps + r0 * PSTR + 8 * nt + 2 * tig) = w0;
            *(float2*)(Ps + (r0 + 8) * PSTR + 8 * nt + 2 * tig) = w1;
        }
        rs0 += __shfl_xor_sync(0xffffffffu, rs0, 1);
        rs0 += __shfl_xor_sync(0xffffffffu, rs0, 2);
        rs1 += __shfl_xor_sync(0xffffffffu, rs1, 1);
        rs1 += __shfl_xor_sync(0xffffffffu, rs1, 2);
        l0 += rs0; l1 += rs1;

        __syncthreads();   // P written by all warps; V tile ready

        // --- O += P @ V  (V read transposed from [key][d] tile)
        const float* Vs = smf + AVS_OFF(st) / 4;
#pragma unroll
        for (int kc = 0; kc < 8; kc++) {
            uint32_t af[4];
            af[0] = __float_as_uint(Ps[r0 * PSTR + 8 * kc + tig]);
            af[1] = __float_as_uint(Ps[(r0 + 8) * PSTR + 8 * kc + tig]);
            af[2] = __float_as_uint(Ps[r0 * PSTR + 8 * kc + tig + 4]);
            af[3] = __float_as_uint(Ps[(r0 + 8) * PSTR + 8 * kc + tig + 4]);
            uint32_t vb[8][2];
#pragma unroll
            for (int nt = 0; nt < 8; nt++) {
                vb[nt][0] = __float_as_uint(Vs[(8 * kc + tig) * KSTR + 8 * nt + g]);
                vb[nt][1] = __float_as_uint(Vs[(8 * kc + tig + 4) * KSTR + 8 * nt + g]);
            }
#pragma unroll
            for (int nt = 0; nt < 8; nt++)
                mma_tf32(o[nt], af, vb[nt]);
        }
        __syncthreads();   // before Ps overwrite / stage reuse next tile
    }

    // --- epilogue: normalize, round to tf32 (feeds proj GEMM), store
    const float inv0 = 1.0f / l0;
    const float inv1 = 1.0f / l1;
    const int b = bh >> 4, h = bh & 15;
    const size_t base0 = ((size_t)b * SS + q0 + r0) * DD + h * 64;
    const size_t base1 = ((size_t)b * SS + q0 + r0 + 8) * DD + h * 64;
#pragma unroll
    for (int nt = 0; nt < 8; nt++) {
        const int col = 8 * nt + 2 * tig;
        float2 w0, w1;
        w0.x = __uint_as_float(f2tf(o[nt][0] * inv0));
        w0.y = __uint_as_float(f2tf(o[nt][1] * inv0));
        w1.x = __uint_as_float(f2tf(o[nt][2] * inv1));
        w1.y = __uint_as_float(f2tf(o[nt][3] * inv1));
        *(float2*)(g_a + base0 + col) = w0;
        *(float2*)(g_a + base1 + col) = w1;
    }
}

// ---------------------------------------------------------------------------
extern "C" void kernel_launch(void* const* d_in, const int* in_sizes, int n_in,
                              void* d_out, int out_size)
{
    const float* x      = (const float*)d_in[0];
    const float* w_attn = (const float*)d_in[1];
    const float* b_attn = (const float*)d_in[2];
    const float* w_proj = (const float*)d_in[3];
    const float* b_proj = (const float*)d_in[4];

    float* out  = (float*)d_out;
    float* kout = out + (size_t)BB * SS * DD;
    float* vout = kout + (size_t)BB * HH * SS * HD;

    float *xr, *war, *wt, *ga, *kr, *vr;
    cudaGetSymbolAddress((void**)&xr, g_xr);
    cudaGetSymbolAddress((void**)&war, g_war);
    cudaGetSymbolAddress((void**)&wt, g_wt);
    cudaGetSymbolAddress((void**)&ga, g_a);
    cudaGetSymbolAddress((void**)&kr, g_kr);
    cudaGetSymbolAddress((void**)&vr, g_vr);

    cudaFuncSetAttribute(mma_gemm<0>, cudaFuncAttributeMaxDynamicSharedMemorySize, GEMM_SMEM);
    cudaFuncSetAttribute(mma_gemm<1>, cudaFuncAttributeMaxDynamicSharedMemorySize, GEMM_SMEM);
    cudaFuncSetAttribute(attn_tc, cudaFuncAttributeMaxDynamicSharedMemorySize, ATT_SMEM);

    // Pre-round GEMM inputs to tf32
    round_kernel<<<1024, 256>>>((const float4*)x, (float4*)xr, BB * SS * DD / 4);
    round_kernel<<<1024, 256>>>((const float4*)w_attn, (float4*)war, 3 * DD * DD / 4);
    transpose_round_kernel<<<dim3(32, 32), dim3(32, 8)>>>(w_proj, wt);

    // QKV GEMM: q(rounded)->g_q, k/v(exact)->present
    mma_gemm<1><<<dim3(3 * DD / 128, BB * SS / 128), 256, GEMM_SMEM>>>(
        xr, war, b_attn, nullptr, kout, vout);

    // Rounded copies of k/v for the attention mma
    round_kernel<<<1024, 256>>>((const float4*)kout, (float4*)kr, BB * HH * SS * HD / 4);
    round_kernel<<<1024, 256>>>((const float4*)vout, (float4*)vr, BB * HH * SS * HD / 4);

    // Tensor-core flash attention -> g_a (tf32-rounded)
    attn_tc<<<dim3(BB * HH, SS / 64), 128, ATT_SMEM>>>(kr, vr);

    // Proj GEMM -> out
    mma_gemm<0><<<dim3(DD / 128, BB * SS / 128), 256, GEMM_SMEM>>>(
        ga, wt, b_proj, out, nullptr, nullptr);
}

// round 5
// speedup vs baseline: 3.8718x; 1.0396x over previous
#include <cuda_runtime.h>
#include <cstdint>

#define BB 4
#define SS 2048
#define DD 1024
#define HH 16
#define HD 64

// Scratch (allocation-free)
__device__ float g_q[(size_t)BB * HH * SS * HD];   // q [B,H,S,hd] (tf32-rounded)
__device__ float g_a[(size_t)BB * SS * DD];        // attention out (tf32-rounded)
__device__ float g_xr[(size_t)BB * SS * DD];       // x rounded to tf32
__device__ float g_war[(size_t)3 * DD * DD];       // w_attn rounded to tf32
__device__ float g_wt[(size_t)DD * DD];            // w_proj^T rounded to tf32
__device__ float g_kr[(size_t)BB * HH * SS * HD];  // k rounded (attention input)
__device__ float g_vr[(size_t)BB * HH * SS * HD];  // v rounded (attention input)

// ---------------------------------------------------------------------------
__device__ __forceinline__ uint32_t smem_u32(const void* p) {
    uint32_t a;
    asm("{ .reg .u64 t; cvta.to.shared.u64 t, %1; cvt.u32.u64 %0, t; }"
        : "=r"(a) : "l"(p));
    return a;
}
__device__ __forceinline__ uint32_t f2tf(float f) {
    uint32_t u;
    asm("cvt.rna.tf32.f32 %0, %1;" : "=r"(u) : "f"(f));
    return u;
}
__device__ __forceinline__ void cp_async16(uint32_t dst, const void* src) {
    asm volatile("cp.async.cg.shared.global [%0], [%1], 16;" :: "r"(dst), "l"(src));
}
#define CP_COMMIT() asm volatile("cp.async.commit_group;" ::: "memory")
#define CP_WAIT(n)  asm volatile("cp.async.wait_group %0;" :: "n"(n) : "memory")

__device__ __forceinline__ void mma_tf32(float* c, const uint32_t* a, const uint32_t* b) {
    asm volatile(
        "mma.sync.aligned.m16n8k8.row.col.f32.tf32.tf32.f32 "
        "{%0,%1,%2,%3}, {%4,%5,%6,%7}, {%8,%9}, {%0,%1,%2,%3};"
        : "+f"(c[0]), "+f"(c[1]), "+f"(c[2]), "+f"(c[3])
        : "r"(a[0]), "r"(a[1]), "r"(a[2]), "r"(a[3]), "r"(b[0]), "r"(b[1]));
}

// ---------------------------------------------------------------------------
// Elementwise round-to-tf32
// ---------------------------------------------------------------------------
__global__ __launch_bounds__(256) void round_kernel(
    const float4* __restrict__ in, float4* __restrict__ out, int n4)
{
    int i = blockIdx.x * blockDim.x + threadIdx.x;
    int stride = gridDim.x * blockDim.x;
    for (; i < n4; i += stride) {
        float4 v = in[i];
        float4 o;
        o.x = __uint_as_float(f2tf(v.x));
        o.y = __uint_as_float(f2tf(v.y));
        o.z = __uint_as_float(f2tf(v.z));
        o.w = __uint_as_float(f2tf(v.w));
        out[i] = o;
    }
}

__global__ __launch_bounds__(256) void transpose_round_kernel(
    const float* __restrict__ in, float* __restrict__ out)
{
    __shared__ float t[32][33];
    const int tx = threadIdx.x, ty = threadIdx.y;
    const int k0 = blockIdx.y * 32;
    const int n0 = blockIdx.x * 32;
#pragma unroll
    for (int i = ty; i < 32; i += 8)
        t[i][tx] = in[(size_t)(k0 + i) * DD + n0 + tx];
    __syncthreads();
#pragma unroll
    for (int i = ty; i < 32; i += 8)
        out[(size_t)(n0 + i) * DD + k0 + tx] = __uint_as_float(f2tf(t[tx][i]));
}

// ---------------------------------------------------------------------------
// tf32 mma.sync GEMM: 128x128 tile, BK=32, 2-stage cp.async, 2 CTAs/SM.
// MODE 0: C -> out0. MODE 1: q->g_q (rounded), k->out1 + g_kr, v->out2 + g_vr.
// ---------------------------------------------------------------------------
#define KDIM 1024
#define NCHUNK (KDIM / 32)
#define STG_F 9216                 // (128+128)*36 floats per stage
#define ROWSTRIDE 36
#define GEMM_SMEM (2 * STG_F * 4)  // 73728 bytes

template <int MODE>
__global__ __launch_bounds__(256, 2) void mma_gemm(
    const float* __restrict__ A, const float* __restrict__ Bm,
    const float* __restrict__ bias,
    float* __restrict__ out0, float* __restrict__ out1, float* __restrict__ out2)
{
    extern __shared__ float sm[];
    const uint32_t sbase = smem_u32(sm);
    const int tid = threadIdx.x;
    const int wid = tid >> 5;
    const int lane = tid & 31;
    const int g = lane >> 2;
    const int tig = lane & 3;
    const int m0 = blockIdx.y * 128;
    const int n0 = blockIdx.x * 128;
    const int wm = (wid & 3) * 32;
    const int wn = (wid >> 2) * 64;

    float c[2][8][4];
#pragma unroll
    for (int i = 0; i < 2; i++)
#pragma unroll
        for (int j = 0; j < 8; j++)
#pragma unroll
            for (int k = 0; k < 4; k++) c[i][j][k] = 0.f;

    const int lrow = tid >> 3;
    const int lcol = (tid & 7) * 4;
    const float* Abase = A + (size_t)m0 * KDIM;
    const float* Bbase = Bm + (size_t)n0 * KDIM;

#define ISSUE(chunk, s) do {                                                        \
    const int _k0 = (chunk) * 32;                                                   \
    const uint32_t _as = sbase + (uint32_t)(s) * STG_F * 4;                         \
    const uint32_t _bs = _as + 4608 * 4;                                            \
    _Pragma("unroll")                                                               \
    for (int _i = 0; _i < 4; _i++) {                                                \
        const int _r = lrow + _i * 32;                                              \
        cp_async16(_as + (uint32_t)(_r * ROWSTRIDE + lcol) * 4,                     \
                   Abase + (size_t)_r * KDIM + _k0 + lcol);                         \
        cp_async16(_bs + (uint32_t)(_r * ROWSTRIDE + lcol) * 4,                     \
                   Bbase + (size_t)_r * KDIM + _k0 + lcol);                         \
    }                                                                               \
    CP_COMMIT();                                                                    \
} while (0)

    ISSUE(0, 0);
    ISSUE(1, 1);

    for (int ch = 0; ch < NCHUNK; ch++) {
        const int s = ch & 1;
        if (ch == NCHUNK - 1) { CP_WAIT(0); } else { CP_WAIT(1); }
        __syncthreads();

        const float* As_ = sm + s * STG_F;
        const float* Bs_ = sm + s * STG_F + 4608;
#pragma unroll
        for (int ks = 0; ks < 4; ks++) {
            const int kc = ks * 8 + tig;
            uint32_t af[2][4], bf[8][2];
#pragma unroll
            for (int mt = 0; mt < 2; mt++) {
                const int r = wm + mt * 16 + g;
                af[mt][0] = __float_as_uint(As_[r * ROWSTRIDE + kc]);
                af[mt][1] = __float_as_uint(As_[(r + 8) * ROWSTRIDE + kc]);
                af[mt][2] = __float_as_uint(As_[r * ROWSTRIDE + kc + 4]);
                af[mt][3] = __float_as_uint(As_[(r + 8) * ROWSTRIDE + kc + 4]);
            }
#pragma unroll
            for (int nt = 0; nt < 8; nt++) {
                const int rn = wn + nt * 8 + g;
                bf[nt][0] = __float_as_uint(Bs_[rn * ROWSTRIDE + kc]);
                bf[nt][1] = __float_as_uint(Bs_[rn * ROWSTRIDE + kc + 4]);
            }
#pragma unroll
            for (int mt = 0; mt < 2; mt++)
#pragma unroll
                for (int nt = 0; nt < 8; nt++)
                    mma_tf32(c[mt][nt], af[mt], bf[nt]);
        }
        __syncthreads();
        if (ch + 2 < NCHUNK) ISSUE(ch + 2, s);
    }

#pragma unroll
    for (int mt = 0; mt < 2; mt++) {
        const int row0 = m0 + wm + mt * 16 + g;
        const int row1 = row0 + 8;
#pragma unroll
        for (int nt = 0; nt < 8; nt++) {
            const int n = n0 + wn + nt * 8 + 2 * tig;
            const float2 bv = *(const float2*)(bias + n);
            float2 v0, v1;
            v0.x = c[mt][nt][0] + bv.x; v0.y = c[mt][nt][1] + bv.y;
            v1.x = c[mt][nt][2] + bv.x; v1.y = c[mt][nt][3] + bv.y;
            if (MODE == 0) {
                *(float2*)(out0 + (size_t)row0 * DD + n) = v0;
                *(float2*)(out0 + (size_t)row1 * DD + n) = v1;
            } else {
                const int part = n >> 10;
                const int hc = n & (DD - 1);
                const int h = hc >> 6;
                const int d = hc & 63;
                const int b0_ = row0 >> 11, s0_ = row0 & (SS - 1);
                const int b1_ = row1 >> 11, s1_ = row1 & (SS - 1);
                const size_t d0 = (((size_t)(b0_ * HH + h)) * SS + s0_) * HD + d;
                const size_t d1 = (((size_t)(b1_ * HH + h)) * SS + s1_) * HD + d;
                float2 r0v, r1v;
                r0v.x = __uint_as_float(f2tf(v0.x)); r0v.y = __uint_as_float(f2tf(v0.y));
                r1v.x = __uint_as_float(f2tf(v1.x)); r1v.y = __uint_as_float(f2tf(v1.y));
                if (part == 0) {
                    *(float2*)(g_q + d0) = r0v;
                    *(float2*)(g_q + d1) = r1v;
                } else if (part == 1) {
                    *(float2*)(out1 + d0) = v0;       // exact -> present
                    *(float2*)(out1 + d1) = v1;
                    *(float2*)(g_kr + d0) = r0v;      // rounded -> attention
                    *(float2*)(g_kr + d1) = r1v;
                } else {
                    *(float2*)(out2 + d0) = v0;
                    *(float2*)(out2 + d1) = v1;
                    *(float2*)(g_vr + d0) = r0v;
                    *(float2*)(g_vr + d1) = r1v;
                }
            }
        }
    }
}

// ---------------------------------------------------------------------------
// Tensor-core causal flash attention.
// CTA: 256 threads (8 warps), 128 queries. Key tiles of 64, cp.async x2 stages.
// Ks/Vs stride 76 floats (conflict-free); Ps stride 68 floats.
// ---------------------------------------------------------------------------
#define KSTR 76
#define PSTR 68
#define KVSTG 19456u                         // 64*76*4
#define AKS_OFF(s) ((uint32_t)(s) * KVSTG)
#define AVS_OFF(s) (2u * KVSTG + (uint32_t)(s) * KVSTG)
#define APS_OFF (4u * KVSTG)                 // 77824
#define ATT_SMEM (APS_OFF + 128u * PSTR * 4u)  // 112640 bytes

__global__ __launch_bounds__(256, 1) void attn_tc(
    const float* __restrict__ kr, const float* __restrict__ vr)
{
    extern __shared__ char smc[];
    float* smf = (float*)smc;
    const uint32_t sb = smem_u32(smc);
    const int tid = threadIdx.x;
    const int w = tid >> 5, lane = tid & 31;
    const int g = lane >> 2, tig = lane & 3;
    const int bh = blockIdx.x;
    const int qblk = blockIdx.y;
    const int q0 = qblk * 128;
    const int tmax = 2 * qblk + 1;          // key tiles 0..tmax (64 keys each)
    const float* kbase = kr + (size_t)bh * SS * HD;
    const float* vbase = vr + (size_t)bh * SS * HD;

#define AISSUE(t) do {                                                            \
    const int _st = (t) & 1;                                                      \
    const int _k0 = (t) * 64;                                                     \
    _Pragma("unroll")                                                             \
    for (int _i = 0; _i < 4; _i++) {                                              \
        const int _f = tid + 256 * _i;                                            \
        const int _r = _f >> 4;                                                   \
        const int _c = (_f & 15) << 2;                                            \
        cp_async16(sb + AKS_OFF(_st) + (uint32_t)(_r * KSTR + _c) * 4,            \
                   kbase + (size_t)(_k0 + _r) * HD + _c);                         \
        cp_async16(sb + AVS_OFF(_st) + (uint32_t)(_r * KSTR + _c) * 4,            \
                   vbase + (size_t)(_k0 + _r) * HD + _c);                         \
    }                                                                             \
    CP_COMMIT();                                                                  \
} while (0)

    // Stage Q (128x64) into Ps region
    {
        const float* qbase = g_q + ((size_t)bh * SS + q0) * HD;
#pragma unroll
        for (int i = 0; i < 8; i++) {
            const int f = tid + 256 * i;
            const int r = f >> 4;
            const int c = (f & 15) << 2;
            cp_async16(sb + APS_OFF + (uint32_t)(r * PSTR + c) * 4,
                       qbase + (size_t)r * HD + c);
        }
        CP_COMMIT();
    }
    AISSUE(0);
    CP_WAIT(1);            // Q staged
    __syncthreads();

    const int r0 = w * 16 + g;              // local query rows r0, r0+8

    // Q fragments (pre-scaled by 1/sqrt(hd)=0.125)
    uint32_t qa[8][4];
    {
        const float* Q = smf + APS_OFF / 4;
#pragma unroll
        for (int kc = 0; kc < 8; kc++) {
            qa[kc][0] = __float_as_uint(Q[r0 * PSTR + kc * 8 + tig] * 0.125f);
            qa[kc][1] = __float_as_uint(Q[(r0 + 8) * PSTR + kc * 8 + tig] * 0.125f);
            qa[kc][2] = __float_as_uint(Q[r0 * PSTR + kc * 8 + tig + 4] * 0.125f);
            qa[kc][3] = __float_as_uint(Q[(r0 + 8) * PSTR + kc * 8 + tig + 4] * 0.125f);
        }
    }
    __syncthreads();

    float o[8][4];
#pragma unroll
    for (int i = 0; i < 8; i++)
#pragma unroll
        for (int j = 0; j < 4; j++) o[i][j] = 0.f;
    float m0 = -1e30f, m1 = -1e30f, l0 = 0.f, l1 = 0.f;

    for (int t = 0; t <= tmax; t++) {
        const int st = t & 1;
        if (t < tmax) AISSUE(t + 1);
        if (t < tmax) { CP_WAIT(1); } else { CP_WAIT(0); }
        __syncthreads();   // K/V stage st visible

        // --- S = (Q/8) @ K^T
        float s[8][4];
#pragma unroll
        for (int i = 0; i < 8; i++)
#pragma unroll
            for (int j = 0; j < 4; j++) s[i][j] = 0.f;

        const float* Ks = smf + AKS_OFF(st) / 4;
#pragma unroll
        for (int kc = 0; kc < 8; kc++) {
            uint32_t kb[8][2];
#pragma unroll
            for (int nt = 0; nt < 8; nt++) {
                kb[nt][0] = __float_as_uint(Ks[(8 * nt + g) * KSTR + 8 * kc + tig]);
                kb[nt][1] = __float_as_uint(Ks[(8 * nt + g) * KSTR + 8 * kc + tig + 4]);
            }
#pragma unroll
            for (int nt = 0; nt < 8; nt++)
                mma_tf32(s[nt], qa[kc], kb[nt]);
        }

        // --- causal mask (last two key tiles only)
        if (t >= 2 * qblk) {
            const int qg0 = q0 + r0;
            const int qg1 = qg0 + 8;
            const int kb0 = t * 64;
#pragma unroll
            for (int nt = 0; nt < 8; nt++) {
                const int col = kb0 + 8 * nt + 2 * tig;
                if (col > qg0)     s[nt][0] = -1e30f;
                if (col + 1 > qg0) s[nt][1] = -1e30f;
                if (col > qg1)     s[nt][2] = -1e30f;
                if (col + 1 > qg1) s[nt][3] = -1e30f;
            }
        }

        // --- row max
        float mx0 = -1e30f, mx1 = -1e30f;
#pragma unroll
        for (int nt = 0; nt < 8; nt++) {
            mx0 = fmaxf(mx0, fmaxf(s[nt][0], s[nt][1]));
            mx1 = fmaxf(mx1, fmaxf(s[nt][2], s[nt][3]));
        }
        mx0 = fmaxf(mx0, __shfl_xor_sync(0xffffffffu, mx0, 1));
        mx0 = fmaxf(mx0, __shfl_xor_sync(0xffffffffu, mx0, 2));
        mx1 = fmaxf(mx1, __shfl_xor_sync(0xffffffffu, mx1, 1));
        mx1 = fmaxf(mx1, __shfl_xor_sync(0xffffffffu, mx1, 2));

        const float mn0 = fmaxf(m0, mx0);
        const float mn1 = fmaxf(m1, mx1);
        const float a0 = __expf(m0 - mn0);
        const float a1 = __expf(m1 - mn1);
        m0 = mn0; m1 = mn1;
        l0 *= a0; l1 *= a1;
#pragma unroll
        for (int nt = 0; nt < 8; nt++) {
            o[nt][0] *= a0; o[nt][1] *= a0;
            o[nt][2] *= a1; o[nt][3] *= a1;
        }

        // --- exp, write P (tf32-rounded) to warp-private Ps rows
        float* Ps = smf + APS_OFF / 4;
        float rs0 = 0.f, rs1 = 0.f;
#pragma unroll
        for (int nt = 0; nt < 8; nt++) {
            const float p0 = __expf(s[nt][0] - mn0);
            const float p1 = __expf(s[nt][1] - mn0);
            const float p2 = __expf(s[nt][2] - mn1);
            const float p3 = __expf(s[nt][3] - mn1);
            rs0 += p0 + p1;
            rs1 += p2 + p3;
            float2 w0, w1;
            w0.x = __uint_as_float(f2tf(p0)); w0.y = __uint_as_float(f2tf(p1));
            w1.x = __uint_as_float(f2tf(p2)); w1.y = __uint_as_float(f2tf(p3));
            *(float2*)(Ps + r0 * PSTR + 8 * nt + 2 * tig) = w0;
            *(float2*)(Ps + (r0 + 8) * PSTR + 8 * nt + 2 * tig) = w1;
        }
        rs0 += __shfl_xor_sync(0xffffffffu, rs0, 1);
        rs0 += __shfl_xor_sync(0xffffffffu, rs0, 2);
        rs1 += __shfl_xor_sync(0xffffffffu, rs1, 1);
        rs1 += __shfl_xor_sync(0xffffffffu, rs1, 2);
        l0 += rs0; l1 += rs1;

        __syncwarp();      // P rows are warp-private; warp-level sync suffices

        // --- O += P @ V
        const float* Vs = smf + AVS_OFF(st) / 4;
#pragma unroll
        for (int kc = 0; kc < 8; kc++) {
            uint32_t af[4];
            af[0] = __float_as_uint(Ps[r0 * PSTR + 8 * kc + tig]);
            af[1] = __float_as_uint(Ps[(r0 + 8) * PSTR + 8 * kc + tig]);
            af[2] = __float_as_uint(Ps[r0 * PSTR + 8 * kc + tig + 4]);
            af[3] = __float_as_uint(Ps[(r0 + 8) * PSTR + 8 * kc + tig + 4]);
            uint32_t vb[8][2];
#pragma unroll
            for (int nt = 0; nt < 8; nt++) {
                vb[nt][0] = __float_as_uint(Vs[(8 * kc + tig) * KSTR + 8 * nt + g]);
                vb[nt][1] = __float_as_uint(Vs[(8 * kc + tig + 4) * KSTR + 8 * nt + g]);
            }
#pragma unroll
            for (int nt = 0; nt < 8; nt++)
                mma_tf32(o[nt], af, vb[nt]);
        }
        __syncthreads();   // all reads of stage st done before next overwrite
    }

    // --- epilogue: normalize, round to tf32, store
    const float inv0 = 1.0f / l0;
    const float inv1 = 1.0f / l1;
    const int b = bh >> 4, h = bh & 15;
    const size_t base0 = ((size_t)b * SS + q0 + r0) * DD + h * 64;
    const size_t base1 = ((size_t)b * SS + q0 + r0 + 8) * DD + h * 64;
#pragma unroll
    for (int nt = 0; nt < 8; nt++) {
        const int col = 8 * nt + 2 * tig;
        float2 w0, w1;
        w0.x = __uint_as_float(f2tf(o[nt][0] * inv0));
        w0.y = __uint_as_float(f2tf(o[nt][1] * inv0));
        w1.x = __uint_as_float(f2tf(o[nt][2] * inv1));
        w1.y = __uint_as_float(f2tf(o[nt][3] * inv1));
        *(float2*)(g_a + base0 + col) = w0;
        *(float2*)(g_a + base1 + col) = w1;
    }
}

// ---------------------------------------------------------------------------
extern "C" void kernel_launch(void* const* d_in, const int* in_sizes, int n_in,
                              void* d_out, int out_size)
{
    const float* x      = (const float*)d_in[0];
    const float* w_attn = (const float*)d_in[1];
    const float* b_attn = (const float*)d_in[2];
    const float* w_proj = (const float*)d_in[3];
    const float* b_proj = (const float*)d_in[4];

    float* out  = (float*)d_out;
    float* kout = out + (size_t)BB * SS * DD;
    float* vout = kout + (size_t)BB * HH * SS * HD;

    float *xr, *war, *wt, *ga, *kr, *vr;
    cudaGetSymbolAddress((void**)&xr, g_xr);
    cudaGetSymbolAddress((void**)&war, g_war);
    cudaGetSymbolAddress((void**)&wt, g_wt);
    cudaGetSymbolAddress((void**)&ga, g_a);
    cudaGetSymbolAddress((void**)&kr, g_kr);
    cudaGetSymbolAddress((void**)&vr, g_vr);

    cudaFuncSetAttribute(mma_gemm<0>, cudaFuncAttributeMaxDynamicSharedMemorySize, GEMM_SMEM);
    cudaFuncSetAttribute(mma_gemm<1>, cudaFuncAttributeMaxDynamicSharedMemorySize, GEMM_SMEM);
    cudaFuncSetAttribute(attn_tc, cudaFuncAttributeMaxDynamicSharedMemorySize, ATT_SMEM);

    // Pre-round GEMM inputs to tf32
    round_kernel<<<1024, 256>>>((const float4*)x, (float4*)xr, BB * SS * DD / 4);
    round_kernel<<<1024, 256>>>((const float4*)w_attn, (float4*)war, 3 * DD * DD / 4);
    transpose_round_kernel<<<dim3(32, 32), dim3(32, 8)>>>(w_proj, wt);

    // QKV GEMM: q(rounded)->g_q, k/v exact->present + rounded->g_kr/g_vr
    mma_gemm<1><<<dim3(3 * DD / 128, BB * SS / 128), 256, GEMM_SMEM>>>(
        xr, war, b_attn, nullptr, kout, vout);

    // Tensor-core flash attention -> g_a (tf32-rounded)
    attn_tc<<<dim3(BB * HH, SS / 128), 256, ATT_SMEM>>>(kr, vr);

    // Proj GEMM -> out
    mma_gemm<0><<<dim3(DD / 128, BB * SS / 128), 256, GEMM_SMEM>>>(
        ga, wt, b_proj, out, nullptr, nullptr);
}